// round 4
// baseline (speedup 1.0000x reference)
#include <cuda_runtime.h>
#include <math.h>

#define D 128
#define MAXN 10000

// Scratch (no allocation allowed -> __device__ globals)
__device__ __align__(16) float g_agg[MAXN * D];
__device__ int   g_deg[MAXN];
__device__ float g_deginv[MAXN];

// ---------------------------------------------------------------------------
// Zero agg + deg each call (kernel must be deterministic across replays)
// ---------------------------------------------------------------------------
__global__ void zero_kernel(int n_agg_f4, int n_nodes) {
    int i = blockIdx.x * blockDim.x + threadIdx.x;
    if (i < n_agg_f4) {
        float4 z = make_float4(0.f, 0.f, 0.f, 0.f);
        reinterpret_cast<float4*>(g_agg)[i] = z;
    }
    if (i < n_nodes) g_deg[i] = 0;
}

// ---------------------------------------------------------------------------
// In-degree: deg[dst] += 1 for every edge.  edge_index is INT32 (JAX default
// x64-disabled downcasts the requested int64 to int32).
// ---------------------------------------------------------------------------
__global__ void deg_kernel(const int* __restrict__ ei, int E) {
    int e = blockIdx.x * blockDim.x + threadIdx.x;
    if (e < E) {
        int dst = ei[E + e];
        atomicAdd(&g_deg[dst], 1);
    }
}

__global__ void deginv_kernel(int n_nodes) {
    int i = blockIdx.x * blockDim.x + threadIdx.x;
    if (i < n_nodes) {
        g_deginv[i] = rsqrtf((float)g_deg[i] + 1.0f);
    }
}

// ---------------------------------------------------------------------------
// Edge scatter: one warp per edge.
//   msg = x[src] * deginv[src] * w_e ; agg[dst] += msg
// Lane l handles floats [4l, 4l+4) of the 128-wide row (vector load, scalar
// atomics -- 16B vector atomicAdd is rejected on this target).
// ---------------------------------------------------------------------------
__global__ void scatter_kernel(const float* __restrict__ x,
                               const int* __restrict__ ei,
                               const float* __restrict__ ew,
                               int E) {
    int gtid = blockIdx.x * blockDim.x + threadIdx.x;
    int e    = gtid >> 5;
    int lane = gtid & 31;
    if (e >= E) return;

    int src = ei[e];
    int dst = ei[E + e];
    float coef = g_deginv[src] * ew[e];

    float4 v = reinterpret_cast<const float4*>(x + (size_t)src * D)[lane];

    float* p = g_agg + (size_t)dst * D + lane * 4;
    atomicAdd(p + 0, v.x * coef);
    atomicAdd(p + 1, v.y * coef);
    atomicAdd(p + 2, v.z * coef);
    atomicAdd(p + 3, v.w * coef);
}

// ---------------------------------------------------------------------------
// Fused epilogue: per node
//   a = agg*deginv + x ; h = gelu(a @ W + b) ; out = LN(h)*gamma + beta
// Block = 128 threads, ROWS=4 rows per block (amortizes W loads 4x).
// Thread t owns output column t for each of its 4 rows.
// ---------------------------------------------------------------------------
__global__ void fused_kernel(const float* __restrict__ x,
                             const float* __restrict__ W,
                             const float* __restrict__ b,
                             const float* __restrict__ gamma,
                             const float* __restrict__ beta,
                             float* __restrict__ out,
                             int n_nodes) {
    const int tid  = threadIdx.x;          // 0..127 = output column
    const int row0 = blockIdx.x * 4;

    __shared__ float s_a[4][D];
    __shared__ float s_sum[4][4];   // [warp][row]
    __shared__ float s_sq[4][4];

    #pragma unroll
    for (int r = 0; r < 4; r++) {
        int row = row0 + r;
        if (row < n_nodes) {
            s_a[r][tid] = g_agg[(size_t)row * D + tid] * g_deginv[row]
                          + x[(size_t)row * D + tid];
        } else {
            s_a[r][tid] = 0.f;
        }
    }
    __syncthreads();

    float acc0 = b[tid], acc1 = acc0, acc2 = acc0, acc3 = acc0;

    #pragma unroll 8
    for (int k = 0; k < D; k++) {
        float w = W[k * D + tid];      // coalesced, L1-resident after first block
        acc0 += s_a[0][k] * w;
        acc1 += s_a[1][k] * w;
        acc2 += s_a[2][k] * w;
        acc3 += s_a[3][k] * w;
    }

    float h[4] = {acc0, acc1, acc2, acc3};

    // exact gelu: 0.5*v*(1+erf(v/sqrt(2)))
    #pragma unroll
    for (int r = 0; r < 4; r++) {
        float v = h[r];
        h[r] = 0.5f * v * (1.0f + erff(v * 0.70710678118654752f));
    }

    // LayerNorm: reduce sum & sumsq of 128 values per row
    float sum[4], sq[4];
    #pragma unroll
    for (int r = 0; r < 4; r++) { sum[r] = h[r]; sq[r] = h[r] * h[r]; }

    #pragma unroll
    for (int off = 16; off > 0; off >>= 1) {
        #pragma unroll
        for (int r = 0; r < 4; r++) {
            sum[r] += __shfl_xor_sync(0xFFFFFFFF, sum[r], off);
            sq[r]  += __shfl_xor_sync(0xFFFFFFFF, sq[r], off);
        }
    }
    int wid = tid >> 5, lane = tid & 31;
    if (lane == 0) {
        #pragma unroll
        for (int r = 0; r < 4; r++) { s_sum[wid][r] = sum[r]; s_sq[wid][r] = sq[r]; }
    }
    __syncthreads();

    float g = gamma[tid], bt = beta[tid];
    #pragma unroll
    for (int r = 0; r < 4; r++) {
        float s = s_sum[0][r] + s_sum[1][r] + s_sum[2][r] + s_sum[3][r];
        float q = s_sq[0][r]  + s_sq[1][r]  + s_sq[2][r]  + s_sq[3][r];
        float mu  = s * (1.0f / D);
        float var = q * (1.0f / D) - mu * mu;
        float rstd = rsqrtf(var + 1e-5f);
        int row = row0 + r;
        if (row < n_nodes) {
            out[(size_t)row * D + tid] = (h[r] - mu) * rstd * g + bt;
        }
    }
}

// ---------------------------------------------------------------------------
// Launch
// Inputs (metadata order): x, edge_index(int32!), edge_weight, W, b, gamma, beta
// ---------------------------------------------------------------------------
extern "C" void kernel_launch(void* const* d_in, const int* in_sizes, int n_in,
                              void* d_out, int out_size) {
    const float* x     = (const float*)d_in[0];
    const int*   ei    = (const int*)d_in[1];
    const float* ew    = (const float*)d_in[2];
    const float* W     = (const float*)d_in[3];
    const float* b     = (const float*)d_in[4];
    const float* gamma = (const float*)d_in[5];
    const float* beta  = (const float*)d_in[6];
    float*       out   = (float*)d_out;

    const int N = in_sizes[0] / D;       // 10000
    const int E = in_sizes[2];           // 640000

    // 1) zero scratch
    int n_agg_f4 = N * (D / 4);
    int zthreads = 256;
    int zblocks  = (n_agg_f4 + zthreads - 1) / zthreads;
    zero_kernel<<<zblocks, zthreads>>>(n_agg_f4, N);

    // 2) degree
    deg_kernel<<<(E + 255) / 256, 256>>>(ei, E);

    // 3) deg_inv
    deginv_kernel<<<(N + 255) / 256, 256>>>(N);

    // 4) edge scatter (one warp per edge)
    long long total_threads = (long long)E * 32;
    int sblocks = (int)((total_threads + 255) / 256);
    scatter_kernel<<<sblocks, 256>>>(x, ei, ew, E);

    // 5) fused residual + GEMM + gelu + layernorm
    fused_kernel<<<(N + 3) / 4, 128>>>(x, W, b, gamma, beta, out, N);
}

// round 5
// speedup vs baseline: 1.6454x; 1.6454x over previous
#include <cuda_runtime.h>
#include <math.h>

#define D 128
#define MAXN 10000
#define MAXE 640000

// Scratch (no allocation allowed -> __device__ globals)
__device__ __align__(16) float g_agg[MAXN * D];
__device__ int   g_deg[MAXN];
__device__ float g_deginv[MAXN];
__device__ int   g_start[MAXN];    // exclusive prefix of deg (bucket starts)
__device__ int   g_cursor[MAXN];   // running fill cursors
__device__ int   g_csrc[MAXE];     // CSR: src per edge slot
__device__ float g_ccoef[MAXE];    // CSR: deginv[src]*ew per edge slot

// ---------------------------------------------------------------------------
// Zero deg each call (kernel must be deterministic across replays)
// ---------------------------------------------------------------------------
__global__ void zero_kernel(int n_nodes) {
    int i = blockIdx.x * blockDim.x + threadIdx.x;
    if (i < n_nodes) g_deg[i] = 0;
}

// ---------------------------------------------------------------------------
// In-degree histogram: deg[dst] += 1  (edge_index is int32)
// ---------------------------------------------------------------------------
__global__ void deg_kernel(const int* __restrict__ ei, int E) {
    int e = blockIdx.x * blockDim.x + threadIdx.x;
    if (e < E) {
        atomicAdd(&g_deg[ei[E + e]], 1);
    }
}

// ---------------------------------------------------------------------------
// Single-block exclusive prefix scan over deg -> g_start, g_cursor.
// 1024 threads, each owns a contiguous chunk; Hillis-Steele over partials.
// ---------------------------------------------------------------------------
__global__ void scan_kernel(int N) {
    __shared__ int s_part[1024];
    const int tid = threadIdx.x;
    const int CH  = (N + 1023) / 1024;
    const int base = tid * CH;

    int sum = 0;
    for (int j = 0; j < CH; j++) {
        int i = base + j;
        if (i < N) sum += g_deg[i];
    }
    s_part[tid] = sum;
    __syncthreads();

    for (int off = 1; off < 1024; off <<= 1) {
        int add = (tid >= off) ? s_part[tid - off] : 0;
        __syncthreads();
        s_part[tid] += add;
        __syncthreads();
    }

    int run = (tid == 0) ? 0 : s_part[tid - 1];
    for (int j = 0; j < CH; j++) {
        int i = base + j;
        if (i < N) {
            g_start[i]  = run;
            g_cursor[i] = run;
            run += g_deg[i];
        }
    }
}

__global__ void deginv_kernel(int n_nodes) {
    int i = blockIdx.x * blockDim.x + threadIdx.x;
    if (i < n_nodes) {
        g_deginv[i] = rsqrtf((float)g_deg[i] + 1.0f);
    }
}

// ---------------------------------------------------------------------------
// Fill CSR buckets: one int atomic per edge (vs 128 float atomics before).
// Stores src and the fully precomputed per-edge coefficient.
// ---------------------------------------------------------------------------
__global__ void fill_kernel(const int* __restrict__ ei,
                            const float* __restrict__ ew,
                            int E) {
    int e = blockIdx.x * blockDim.x + threadIdx.x;
    if (e < E) {
        int src = ei[e];
        int dst = ei[E + e];
        int pos = atomicAdd(&g_cursor[dst], 1);
        g_csrc[pos]  = src;
        g_ccoef[pos] = g_deginv[src] * ew[e];
    }
}

// ---------------------------------------------------------------------------
// Gather-reduce: one warp per node. Lane l owns columns [4l, 4l+4) (float4).
// Edge meta staged through shared (broadcast reads, conflict-free).
// agg[dst] = sum_e x[src_e] * coef_e   (single coalesced store, no atomics)
// ---------------------------------------------------------------------------
__global__ void gather_kernel(const float* __restrict__ x, int N) {
    __shared__ int   s_src[8][32];
    __shared__ float s_cf[8][32];

    const int wid  = threadIdx.x >> 5;
    const int lane = threadIdx.x & 31;
    const int row  = blockIdx.x * 8 + wid;
    if (row >= N) return;

    const int s0   = g_start[row];
    const int dcnt = g_deg[row];

    float4 acc = make_float4(0.f, 0.f, 0.f, 0.f);

    for (int base = 0; base < dcnt; base += 32) {
        int idx = base + lane;
        if (idx < dcnt) {
            s_src[wid][lane] = g_csrc[s0 + idx];
            s_cf[wid][lane]  = g_ccoef[s0 + idx];
        }
        __syncwarp();

        int m = dcnt - base;
        if (m >= 32) {
            #pragma unroll 8
            for (int k = 0; k < 32; k++) {
                int   s = s_src[wid][k];
                float c = s_cf[wid][k];
                float4 v = reinterpret_cast<const float4*>(x + (size_t)s * D)[lane];
                acc.x += v.x * c; acc.y += v.y * c;
                acc.z += v.z * c; acc.w += v.w * c;
            }
        } else {
            for (int k = 0; k < m; k++) {
                int   s = s_src[wid][k];
                float c = s_cf[wid][k];
                float4 v = reinterpret_cast<const float4*>(x + (size_t)s * D)[lane];
                acc.x += v.x * c; acc.y += v.y * c;
                acc.z += v.z * c; acc.w += v.w * c;
            }
        }
        __syncwarp();
    }

    reinterpret_cast<float4*>(g_agg + (size_t)row * D)[lane] = acc;
}

// ---------------------------------------------------------------------------
// Fused epilogue: per node
//   a = agg*deginv + x ; h = gelu(a @ W + b) ; out = LN(h)*gamma + beta
// Block = 128 threads, 4 rows per block (amortizes W loads 4x).
// ---------------------------------------------------------------------------
__global__ void fused_kernel(const float* __restrict__ x,
                             const float* __restrict__ W,
                             const float* __restrict__ b,
                             const float* __restrict__ gamma,
                             const float* __restrict__ beta,
                             float* __restrict__ out,
                             int n_nodes) {
    const int tid  = threadIdx.x;          // 0..127 = output column
    const int row0 = blockIdx.x * 4;

    __shared__ float s_a[4][D];
    __shared__ float s_sum[4][4];   // [warp][row]
    __shared__ float s_sq[4][4];

    #pragma unroll
    for (int r = 0; r < 4; r++) {
        int row = row0 + r;
        if (row < n_nodes) {
            s_a[r][tid] = g_agg[(size_t)row * D + tid] * g_deginv[row]
                          + x[(size_t)row * D + tid];
        } else {
            s_a[r][tid] = 0.f;
        }
    }
    __syncthreads();

    float acc0 = b[tid], acc1 = acc0, acc2 = acc0, acc3 = acc0;

    #pragma unroll 8
    for (int k = 0; k < D; k++) {
        float w = W[k * D + tid];      // coalesced, L1-resident after first block
        acc0 += s_a[0][k] * w;
        acc1 += s_a[1][k] * w;
        acc2 += s_a[2][k] * w;
        acc3 += s_a[3][k] * w;
    }

    float h[4] = {acc0, acc1, acc2, acc3};

    // exact gelu: 0.5*v*(1+erf(v/sqrt(2)))
    #pragma unroll
    for (int r = 0; r < 4; r++) {
        float v = h[r];
        h[r] = 0.5f * v * (1.0f + erff(v * 0.70710678118654752f));
    }

    float sum[4], sq[4];
    #pragma unroll
    for (int r = 0; r < 4; r++) { sum[r] = h[r]; sq[r] = h[r] * h[r]; }

    #pragma unroll
    for (int off = 16; off > 0; off >>= 1) {
        #pragma unroll
        for (int r = 0; r < 4; r++) {
            sum[r] += __shfl_xor_sync(0xFFFFFFFF, sum[r], off);
            sq[r]  += __shfl_xor_sync(0xFFFFFFFF, sq[r], off);
        }
    }
    int wid = tid >> 5, lane = tid & 31;
    if (lane == 0) {
        #pragma unroll
        for (int r = 0; r < 4; r++) { s_sum[wid][r] = sum[r]; s_sq[wid][r] = sq[r]; }
    }
    __syncthreads();

    float g = gamma[tid], bt = beta[tid];
    #pragma unroll
    for (int r = 0; r < 4; r++) {
        float s = s_sum[0][r] + s_sum[1][r] + s_sum[2][r] + s_sum[3][r];
        float q = s_sq[0][r]  + s_sq[1][r]  + s_sq[2][r]  + s_sq[3][r];
        float mu  = s * (1.0f / D);
        float var = q * (1.0f / D) - mu * mu;
        float rstd = rsqrtf(var + 1e-5f);
        int row = row0 + r;
        if (row < n_nodes) {
            out[(size_t)row * D + tid] = (h[r] - mu) * rstd * g + bt;
        }
    }
}

// ---------------------------------------------------------------------------
// Launch
// Inputs (metadata order): x, edge_index(int32), edge_weight, W, b, gamma, beta
// ---------------------------------------------------------------------------
extern "C" void kernel_launch(void* const* d_in, const int* in_sizes, int n_in,
                              void* d_out, int out_size) {
    const float* x     = (const float*)d_in[0];
    const int*   ei    = (const int*)d_in[1];
    const float* ew    = (const float*)d_in[2];
    const float* W     = (const float*)d_in[3];
    const float* b     = (const float*)d_in[4];
    const float* gamma = (const float*)d_in[5];
    const float* beta  = (const float*)d_in[6];
    float*       out   = (float*)d_out;

    const int N = in_sizes[0] / D;       // 10000
    const int E = in_sizes[2];           // 640000

    // 1) zero degree histogram
    zero_kernel<<<(N + 255) / 256, 256>>>(N);

    // 2) degree histogram
    deg_kernel<<<(E + 255) / 256, 256>>>(ei, E);

    // 3) bucket offsets (exclusive scan) + cursors
    scan_kernel<<<1, 1024>>>(N);

    // 4) deg_inv
    deginv_kernel<<<(N + 255) / 256, 256>>>(N);

    // 5) fill CSR buckets (1 int atomic per edge)
    fill_kernel<<<(E + 255) / 256, 256>>>(ei, ew, E);

    // 6) gather-reduce per node (no float atomics)
    gather_kernel<<<(N + 7) / 8, 256>>>(x, N);

    // 7) fused residual + GEMM + gelu + layernorm
    fused_kernel<<<(N + 3) / 4, 128>>>(x, W, b, gamma, beta, out, N);
}

// round 8
// speedup vs baseline: 2.3332x; 1.4181x over previous
#include <cuda_runtime.h>
#include <math.h>

#define D 128
#define MAXN 10000
#define MAXE 640000

// Scratch (no allocation allowed -> __device__ globals)
__device__ int   g_deg[MAXN];
__device__ float g_deginv[MAXN];
__device__ int   g_start[MAXN];    // exclusive prefix of deg (bucket starts)
__device__ int   g_cursor[MAXN];   // running fill cursors
__device__ int   g_csrc[MAXE];     // CSR: src per edge slot
__device__ float g_ccoef[MAXE];    // CSR: deginv[src]*ew per edge slot

// ---------------------------------------------------------------------------
// Zero deg each call (kernel must be deterministic across replays)
// ---------------------------------------------------------------------------
__global__ void zero_kernel(int n_nodes) {
    int i = blockIdx.x * blockDim.x + threadIdx.x;
    if (i < n_nodes) g_deg[i] = 0;
}

// ---------------------------------------------------------------------------
// In-degree histogram: deg[dst] += 1  (edge_index is int32)
// ---------------------------------------------------------------------------
__global__ void deg_kernel(const int* __restrict__ ei, int E) {
    int e = blockIdx.x * blockDim.x + threadIdx.x;
    if (e < E) {
        atomicAdd(&g_deg[ei[E + e]], 1);
    }
}

// ---------------------------------------------------------------------------
// Single-block exclusive prefix scan over deg -> g_start, g_cursor.
// Also computes deginv = rsqrt(deg+1) (fused, saves a launch).
// ---------------------------------------------------------------------------
__global__ void scan_kernel(int N) {
    __shared__ int s_part[1024];
    const int tid = threadIdx.x;
    const int CH  = (N + 1023) / 1024;
    const int base = tid * CH;

    int sum = 0;
    for (int j = 0; j < CH; j++) {
        int i = base + j;
        if (i < N) sum += g_deg[i];
    }
    s_part[tid] = sum;
    __syncthreads();

    for (int off = 1; off < 1024; off <<= 1) {
        int add = (tid >= off) ? s_part[tid - off] : 0;
        __syncthreads();
        s_part[tid] += add;
        __syncthreads();
    }

    int run = (tid == 0) ? 0 : s_part[tid - 1];
    for (int j = 0; j < CH; j++) {
        int i = base + j;
        if (i < N) {
            int d = g_deg[i];
            g_start[i]  = run;
            g_cursor[i] = run;
            g_deginv[i] = rsqrtf((float)d + 1.0f);
            run += d;
        }
    }
}

// ---------------------------------------------------------------------------
// Fill CSR buckets: one int atomic per edge.
// Stores src and the fully precomputed per-edge coefficient.
// ---------------------------------------------------------------------------
__global__ void fill_kernel(const int* __restrict__ ei,
                            const float* __restrict__ ew,
                            int E) {
    int e = blockIdx.x * blockDim.x + threadIdx.x;
    if (e < E) {
        int src = ei[e];
        int dst = ei[E + e];
        int pos = atomicAdd(&g_cursor[dst], 1);
        g_csrc[pos]  = src;
        g_ccoef[pos] = g_deginv[src] * ew[e];
    }
}

// ---------------------------------------------------------------------------
// Mega kernel: gather-reduce + residual + GEMM + GELU + LayerNorm.
// Block = 256 threads (8 warps) handles 8 rows.
//  Phase 1: warp w gathers row (blockIdx*8+w); lane l owns cols [4l,4l+4).
//           a = agg*deginv + x  -> shared s_a[w][128]
//  Phase 2: thread t: col = t&127, half = t>>7; computes 4 rows' outputs.
//  Phase 3: GELU + LayerNorm reduction per row, store.
// ---------------------------------------------------------------------------
__global__ void mega_kernel(const float* __restrict__ x,
                            const float* __restrict__ W,
                            const float* __restrict__ b,
                            const float* __restrict__ gamma,
                            const float* __restrict__ beta,
                            float* __restrict__ out,
                            int N) {
    __shared__ float s_a[8][D];
    __shared__ int   s_src[8][32];
    __shared__ float s_cf[8][32];
    __shared__ float s_sum[8][4];    // [row][warp-in-half]
    __shared__ float s_sq[8][4];

    const int tid  = threadIdx.x;
    const int wid  = tid >> 5;
    const int lane = tid & 31;
    const int row0 = blockIdx.x * 8;

    // ---- Phase 1: gather own row ----
    {
        const int row = row0 + wid;
        if (row < N) {
            const int s0   = g_start[row];
            const int dcnt = g_deg[row];
            float4 acc = make_float4(0.f, 0.f, 0.f, 0.f);

            for (int base = 0; base < dcnt; base += 32) {
                int idx = base + lane;
                if (idx < dcnt) {
                    s_src[wid][lane] = g_csrc[s0 + idx];
                    s_cf[wid][lane]  = g_ccoef[s0 + idx];
                }
                __syncwarp();

                int m = dcnt - base;
                if (m >= 32) {
                    #pragma unroll 8
                    for (int k = 0; k < 32; k++) {
                        int   s = s_src[wid][k];
                        float c = s_cf[wid][k];
                        float4 v = reinterpret_cast<const float4*>(x + (size_t)s * D)[lane];
                        acc.x += v.x * c; acc.y += v.y * c;
                        acc.z += v.z * c; acc.w += v.w * c;
                    }
                } else {
                    for (int k = 0; k < m; k++) {
                        int   s = s_src[wid][k];
                        float c = s_cf[wid][k];
                        float4 v = reinterpret_cast<const float4*>(x + (size_t)s * D)[lane];
                        acc.x += v.x * c; acc.y += v.y * c;
                        acc.z += v.z * c; acc.w += v.w * c;
                    }
                }
                __syncwarp();
            }

            float di = g_deginv[row];
            float4 xr = reinterpret_cast<const float4*>(x + (size_t)row * D)[lane];
            float* pa = &s_a[wid][lane * 4];
            pa[0] = acc.x * di + xr.x;
            pa[1] = acc.y * di + xr.y;
            pa[2] = acc.z * di + xr.z;
            pa[3] = acc.w * di + xr.w;
        } else {
            float* pa = &s_a[wid][lane * 4];
            pa[0] = pa[1] = pa[2] = pa[3] = 0.f;
        }
    }
    __syncthreads();

    // ---- Phase 2: GEMM. half = 0 -> rows 0..3, half = 1 -> rows 4..7 ----
    const int col  = tid & 127;
    const int half = tid >> 7;
    const int r0   = half * 4;

    float acc0 = b[col], acc1 = acc0, acc2 = acc0, acc3 = acc0;

    #pragma unroll 8
    for (int k = 0; k < D; k++) {
        float w = W[k * D + col];     // coalesced, L1-resident
        acc0 += s_a[r0 + 0][k] * w;
        acc1 += s_a[r0 + 1][k] * w;
        acc2 += s_a[r0 + 2][k] * w;
        acc3 += s_a[r0 + 3][k] * w;
    }

    float h[4] = {acc0, acc1, acc2, acc3};

    // exact gelu
    #pragma unroll
    for (int r = 0; r < 4; r++) {
        float v = h[r];
        h[r] = 0.5f * v * (1.0f + erff(v * 0.70710678118654752f));
    }

    // ---- Phase 3: LayerNorm over 128 cols (per row) ----
    float sum[4], sq[4];
    #pragma unroll
    for (int r = 0; r < 4; r++) { sum[r] = h[r]; sq[r] = h[r] * h[r]; }

    #pragma unroll
    for (int off = 16; off > 0; off >>= 1) {
        #pragma unroll
        for (int r = 0; r < 4; r++) {
            sum[r] += __shfl_xor_sync(0xFFFFFFFF, sum[r], off);
            sq[r]  += __shfl_xor_sync(0xFFFFFFFF, sq[r], off);
        }
    }
    const int wih = (tid >> 5) & 3;   // warp index within the half (0..3)
    if (lane == 0) {
        #pragma unroll
        for (int r = 0; r < 4; r++) {
            s_sum[r0 + r][wih] = sum[r];
            s_sq[r0 + r][wih]  = sq[r];
        }
    }
    __syncthreads();

    float g = gamma[col], bt = beta[col];
    #pragma unroll
    for (int r = 0; r < 4; r++) {
        int rr = r0 + r;
        float s = s_sum[rr][0] + s_sum[rr][1] + s_sum[rr][2] + s_sum[rr][3];
        float q = s_sq[rr][0]  + s_sq[rr][1]  + s_sq[rr][2]  + s_sq[rr][3];
        float mu  = s * (1.0f / D);
        float var = q * (1.0f / D) - mu * mu;
        float rstd = rsqrtf(var + 1e-5f);
        int row = row0 + rr;
        if (row < N) {
            out[(size_t)row * D + col] = (h[r] - mu) * rstd * g + bt;
        }
    }
}

// ---------------------------------------------------------------------------
// Launch
// Inputs (metadata order): x, edge_index(int32), edge_weight, W, b, gamma, beta
// ---------------------------------------------------------------------------
extern "C" void kernel_launch(void* const* d_in, const int* in_sizes, int n_in,
                              void* d_out, int out_size) {
    const float* x     = (const float*)d_in[0];
    const int*   ei    = (const int*)d_in[1];
    const float* ew    = (const float*)d_in[2];
    const float* W     = (const float*)d_in[3];
    const float* b     = (const float*)d_in[4];
    const float* gamma = (const float*)d_in[5];
    const float* beta  = (const float*)d_in[6];
    float*       out   = (float*)d_out;

    const int N = in_sizes[0] / D;       // 10000
    const int E = in_sizes[2];           // 640000

    zero_kernel<<<(N + 255) / 256, 256>>>(N);
    deg_kernel<<<(E + 255) / 256, 256>>>(ei, E);
    scan_kernel<<<1, 1024>>>(N);                       // + deginv + cursors
    fill_kernel<<<(E + 255) / 256, 256>>>(ei, ew, E);
    mega_kernel<<<(N + 7) / 8, 256>>>(x, W, b, gamma, beta, out, N);
}